// round 1
// baseline (speedup 1.0000x reference)
#include <cuda_runtime.h>
#include <math.h>

#define BDIM 32
#define TDIM 1024
#define DDIM 512
#define KDIM 64
#define K2   128
#define HDIM 4
#define KPD  16
#define MLPD 2048
#define BT   (BDIM * TDIM)

// ---------------- scratch (static device arrays; no allocation) -------------
__device__ float g_xn[(size_t)BT * DDIM];
__device__ float g_beta[(size_t)BT * K2];
__device__ float g_craw[(size_t)BT * K2];
__device__ float g_gpre[(size_t)BT * DDIM];
__device__ float g_h[(size_t)BT * DDIM];
__device__ float g_x1[(size_t)BT * DDIM];
__device__ float g_xn2[(size_t)BT * DDIM];
__device__ float g_t1[(size_t)BT * MLPD];

// ---------------- LayerNorm: one block per row (512 cols, 256 threads) ------
__global__ void ln_kernel(const float* __restrict__ x, const float* __restrict__ g,
                          const float* __restrict__ b, float* __restrict__ y) {
    int row = blockIdx.x;
    int tid = threadIdx.x;
    const float* xr = x + (size_t)row * DDIM;
    float v0 = xr[tid], v1 = xr[tid + 256];
    float s = v0 + v1, sq = v0 * v0 + v1 * v1;
    __shared__ float rs[8], rq[8];
    #pragma unroll
    for (int o = 16; o > 0; o >>= 1) {
        s  += __shfl_down_sync(0xffffffffu, s, o);
        sq += __shfl_down_sync(0xffffffffu, sq, o);
    }
    if ((tid & 31) == 0) { rs[tid >> 5] = s; rq[tid >> 5] = sq; }
    __syncthreads();
    __shared__ float mean_s, rstd_s;
    if (tid == 0) {
        float ts = 0.f, tq = 0.f;
        #pragma unroll
        for (int i = 0; i < 8; i++) { ts += rs[i]; tq += rq[i]; }
        float m = ts * (1.0f / DDIM);
        float var = tq * (1.0f / DDIM) - m * m;
        mean_s = m; rstd_s = rsqrtf(var + 1e-5f);
    }
    __syncthreads();
    float m = mean_s, r = rstd_s;
    float* yr = y + (size_t)row * DDIM;
    yr[tid]       = (v0 - m) * r * g[tid]       + b[tid];
    yr[tid + 256] = (v1 - m) * r * g[tid + 256] + b[tid + 256];
}

// ---- fused: x1 = x + sigmoid(gpre + b_gate) * h ; xn2 = LN(x1, g2, bn2) -----
__global__ void gate_ln_kernel(const float* __restrict__ x, const float* __restrict__ gpre,
                               const float* __restrict__ bg, const float* __restrict__ h,
                               const float* __restrict__ g2, const float* __restrict__ bn2,
                               float* __restrict__ x1, float* __restrict__ xn2) {
    int row = blockIdx.x;
    int tid = threadIdx.x;
    size_t base = (size_t)row * DDIM;
    int c0 = tid, c1 = tid + 256;
    float gp0 = gpre[base + c0] + bg[c0];
    float gp1 = gpre[base + c1] + bg[c1];
    float v0 = x[base + c0] + (1.0f / (1.0f + expf(-gp0))) * h[base + c0];
    float v1 = x[base + c1] + (1.0f / (1.0f + expf(-gp1))) * h[base + c1];
    x1[base + c0] = v0;
    x1[base + c1] = v1;
    float s = v0 + v1, sq = v0 * v0 + v1 * v1;
    __shared__ float rs[8], rq[8];
    #pragma unroll
    for (int o = 16; o > 0; o >>= 1) {
        s  += __shfl_down_sync(0xffffffffu, s, o);
        sq += __shfl_down_sync(0xffffffffu, sq, o);
    }
    if ((tid & 31) == 0) { rs[tid >> 5] = s; rq[tid >> 5] = sq; }
    __syncthreads();
    __shared__ float mean_s, rstd_s;
    if (tid == 0) {
        float ts = 0.f, tq = 0.f;
        #pragma unroll
        for (int i = 0; i < 8; i++) { ts += rs[i]; tq += rq[i]; }
        float m = ts * (1.0f / DDIM);
        float var = tq * (1.0f / DDIM) - m * m;
        mean_s = m; rstd_s = rsqrtf(var + 1e-5f);
    }
    __syncthreads();
    float m = mean_s, r = rstd_s;
    xn2[base + c0] = (v0 - m) * r * g2[c0] + bn2[c0];
    xn2[base + c1] = (v1 - m) * r * g2[c1] + bn2[c1];
}

// ---------------- complex linear recurrence (causal conv with lambda^n) -----
// c[t] = lambda * c[t-1] + beta[t], lambda_k = sigmoid(log_decay_k)*e^{i freq_k}
// One block per batch b; 128 threads; smem-staged chunks of 64 timesteps.
__global__ void scan_kernel(const float* __restrict__ beta, const float* __restrict__ log_decay,
                            const float* __restrict__ freq, float* __restrict__ craw) {
    __shared__ float s[64 * 128];
    int b = blockIdx.x;
    int tid = threadIdx.x;
    float lr = 0.f, li = 0.f, cr = 0.f, ci = 0.f;
    if (tid < 64) {
        float mag = 1.0f / (1.0f + expf(-log_decay[tid]));
        float sn, cs;
        sincosf(freq[tid], &sn, &cs);
        lr = mag * cs;
        li = mag * sn;
    }
    for (int chunk = 0; chunk < 16; chunk++) {
        size_t base = ((size_t)b * TDIM + chunk * 64) * K2;
        const float4* src = (const float4*)(beta + base);
        float4* dst = (float4*)s;
        #pragma unroll
        for (int i = 0; i < 16; i++) dst[tid + i * 128] = src[tid + i * 128];
        __syncthreads();
        if (tid < 64) {
            #pragma unroll 4
            for (int t = 0; t < 64; t++) {
                float br = s[t * 128 + tid];
                float bi = s[t * 128 + 64 + tid];
                float nr = fmaf(lr, cr, fmaf(-li, ci, br));
                float ni = fmaf(lr, ci, fmaf(li, cr, bi));
                cr = nr; ci = ni;
                s[t * 128 + tid] = cr;
                s[t * 128 + 64 + tid] = ci;
            }
        }
        __syncthreads();
        float4* out = (float4*)(craw + base);
        const float4* ssrc = (const float4*)s;
        #pragma unroll
        for (int i = 0; i < 16; i++) out[tid + i * 128] = ssrc[tid + i * 128];
        __syncthreads();
    }
}

// ------------- per-head coupling: eig[...,h,j] = sum_k coup[h,j,k]*c[...,h,k]
// 256 threads = 4 tokens x 64 output cols; handles real+imag per thread.
__global__ void coupling_kernel(const float* __restrict__ craw, const float* __restrict__ coup,
                                float* __restrict__ eig) {
    __shared__ float sc[HDIM * KPD * KPD];   // 1024
    __shared__ float row[4 * K2];            // 512
    int tid = threadIdx.x;
    #pragma unroll
    for (int i = tid; i < HDIM * KPD * KPD; i += 256) sc[i] = coup[i];
    const float2* src = (const float2*)(craw + (size_t)blockIdx.x * 4 * K2);
    ((float2*)row)[tid] = src[tid];
    __syncthreads();
    int local = tid >> 6;            // token within block
    int j = tid & 63;                // output eigenstate index
    int h = j >> 4, jj = j & 15;
    const float* cp = &sc[h * 256 + jj * 16];
    const float* rr = &row[local * K2 + h * 16];
    float accr = 0.f, acci = 0.f;
    #pragma unroll
    for (int k = 0; k < 16; k++) {
        accr = fmaf(cp[k], rr[k], accr);
        acci = fmaf(cp[k], rr[k + 64], acci);
    }
    size_t token = (size_t)blockIdx.x * 4 + local;
    eig[token * K2 + j] = accr;
    eig[token * K2 + 64 + j] = acci;
}

// ---------------- SGEMM 128x128x8, 256 threads, 8x8 per thread --------------
// EPI: 0 = store; 1 = silu(c + bias[n]); 2 = c + bias[n] + res[row*N+n]
template <int EPI>
__global__ void __launch_bounds__(256) sgemm(const float* __restrict__ A, const float* __restrict__ B,
                                             float* __restrict__ C, int M, int N, int K,
                                             const float* __restrict__ bias,
                                             const float* __restrict__ res) {
    __shared__ float As[8][128];
    __shared__ float Bs[8][128];
    const int tid = threadIdx.x;
    const int bm = blockIdx.y * 128;
    const int bn = blockIdx.x * 128;
    const int tx = (tid & 15) * 8;
    const int ty = (tid >> 4) * 8;
    float acc[8][8];
    #pragma unroll
    for (int i = 0; i < 8; i++)
        #pragma unroll
        for (int j = 0; j < 8; j++) acc[i][j] = 0.f;

    const int arow = tid >> 1;
    const int acol = (tid & 1) * 4;
    const int brow = tid >> 5;
    const int bcol = (tid & 31) * 4;
    const float* Aptr = A + (size_t)(bm + arow) * K + acol;
    const float* Bptr = B + (size_t)brow * N + bn + bcol;

    for (int k0 = 0; k0 < K; k0 += 8) {
        float4 av = *(const float4*)Aptr;
        float4 bv = *(const float4*)Bptr;
        Aptr += 8;
        Bptr += (size_t)8 * N;
        As[acol + 0][arow] = av.x;
        As[acol + 1][arow] = av.y;
        As[acol + 2][arow] = av.z;
        As[acol + 3][arow] = av.w;
        *(float4*)&Bs[brow][bcol] = bv;
        __syncthreads();
        #pragma unroll
        for (int k = 0; k < 8; k++) {
            float a[8], bb[8];
            *(float4*)(a)      = *(const float4*)&As[k][ty];
            *(float4*)(a + 4)  = *(const float4*)&As[k][ty + 4];
            *(float4*)(bb)     = *(const float4*)&Bs[k][tx];
            *(float4*)(bb + 4) = *(const float4*)&Bs[k][tx + 4];
            #pragma unroll
            for (int i = 0; i < 8; i++)
                #pragma unroll
                for (int j = 0; j < 8; j++)
                    acc[i][j] = fmaf(a[i], bb[j], acc[i][j]);
        }
        __syncthreads();
    }

    #pragma unroll
    for (int i = 0; i < 8; i++) {
        size_t r = (size_t)(bm + ty + i);
        float* crow = C + r * N + bn + tx;
        #pragma unroll
        for (int j = 0; j < 8; j++) {
            float v = acc[i][j];
            int c = bn + tx + j;
            if (EPI == 1) {
                v += bias[c];
                v = v / (1.0f + expf(-v));        // silu
            } else if (EPI == 2) {
                v += bias[c] + res[r * N + c];
            }
            crow[j] = v;
        }
    }
}

// -----------------------------------------------------------------------------
extern "C" void kernel_launch(void* const* d_in, const int* in_sizes, int n_in,
                              void* d_out, int out_size) {
    const float* x         = (const float*)d_in[0];
    const float* w_in      = (const float*)d_in[1];
    const float* log_decay = (const float*)d_in[2];
    const float* frequency = (const float*)d_in[3];
    const float* coupling  = (const float*)d_in[4];
    const float* w_out     = (const float*)d_in[5];
    const float* w_gate    = (const float*)d_in[6];
    const float* b_gate    = (const float*)d_in[7];
    const float* w1        = (const float*)d_in[8];
    const float* b1        = (const float*)d_in[9];
    const float* w2        = (const float*)d_in[10];
    const float* b2        = (const float*)d_in[11];
    const float* g1        = (const float*)d_in[12];
    const float* bn1       = (const float*)d_in[13];
    const float* g2        = (const float*)d_in[14];
    const float* bn2       = (const float*)d_in[15];

    float* out = (float*)d_out;
    float* eig = out + (size_t)BT * DDIM;   // outputs: (out, eigenstates) concat

    float *xn, *beta, *craw, *gpre, *h, *x1, *xn2, *t1;
    cudaGetSymbolAddress((void**)&xn,   g_xn);
    cudaGetSymbolAddress((void**)&beta, g_beta);
    cudaGetSymbolAddress((void**)&craw, g_craw);
    cudaGetSymbolAddress((void**)&gpre, g_gpre);
    cudaGetSymbolAddress((void**)&h,    g_h);
    cudaGetSymbolAddress((void**)&x1,   g_x1);
    cudaGetSymbolAddress((void**)&xn2,  g_xn2);
    cudaGetSymbolAddress((void**)&t1,   g_t1);

    // 1. xn = LN(x)
    ln_kernel<<<BT, 256>>>(x, g1, bn1, xn);
    // 2. beta = xn @ w_in   [BT,512]x[512,128]
    sgemm<0><<<dim3(K2 / 128, BT / 128), 256>>>(xn, w_in, beta, BT, K2, DDIM, nullptr, nullptr);
    // 3. complex causal recurrence over T
    scan_kernel<<<BDIM, 128>>>(beta, log_decay, frequency, craw);
    // 4. per-head coupling -> eigenstates (second output)
    coupling_kernel<<<BT / 4, 256>>>(craw, coupling, eig);
    // 5. h = eigenstates @ w_out   [BT,128]x[128,512]
    sgemm<0><<<dim3(DDIM / 128, BT / 128), 256>>>(eig, w_out, h, BT, DDIM, K2, nullptr, nullptr);
    // 6. gate_pre = xn @ w_gate   [BT,512]x[512,512]
    sgemm<0><<<dim3(DDIM / 128, BT / 128), 256>>>(xn, w_gate, gpre, BT, DDIM, DDIM, nullptr, nullptr);
    // 7. x1 = x + sigmoid(gate_pre+b_gate)*h ; xn2 = LN(x1)
    gate_ln_kernel<<<BT, 256>>>(x, gpre, b_gate, h, g2, bn2, x1, xn2);
    // 8. t1 = silu(xn2 @ w1 + b1)   [BT,512]x[512,2048]
    sgemm<1><<<dim3(MLPD / 128, BT / 128), 256>>>(xn2, w1, t1, BT, MLPD, DDIM, b1, nullptr);
    // 9. out = x1 + t1 @ w2 + b2   [BT,2048]x[2048,512]
    sgemm<2><<<dim3(DDIM / 128, BT / 128), 256>>>(t1, w2, out, BT, DDIM, MLPD, b2, x1);
}

// round 3
// speedup vs baseline: 2.5132x; 2.5132x over previous
#include <cuda_runtime.h>
#include <cuda_bf16.h>
#include <math.h>
#include <stdint.h>

#define BDIM 32
#define TDIM 1024
#define DDIM 512
#define K2   128
#define HDIM 4
#define KPD  16
#define MLPD 2048
#define BT   (BDIM * TDIM)

// ---------------- scratch (static device arrays; no allocation) -------------
__device__ float g_beta[(size_t)BT * K2];
__device__ float g_craw[(size_t)BT * K2];
__device__ float g_gpre[(size_t)BT * DDIM];
__device__ float g_h   [(size_t)BT * DDIM];
__device__ float g_x1  [(size_t)BT * DDIM];
__device__ __nv_bfloat16 g_xn_h [(size_t)BT * DDIM], g_xn_l [(size_t)BT * DDIM];
__device__ __nv_bfloat16 g_xn2_h[(size_t)BT * DDIM], g_xn2_l[(size_t)BT * DDIM];
__device__ __nv_bfloat16 g_eig_h[(size_t)BT * K2],   g_eig_l[(size_t)BT * K2];
__device__ __nv_bfloat16 g_t1_h [(size_t)BT * MLPD], g_t1_l [(size_t)BT * MLPD];
// transposed weights [N, K] as bf16 hi/lo
__device__ __nv_bfloat16 g_wi_h[K2 * DDIM],   g_wi_l[K2 * DDIM];
__device__ __nv_bfloat16 g_wo_h[DDIM * K2],   g_wo_l[DDIM * K2];
__device__ __nv_bfloat16 g_wg_h[DDIM * DDIM], g_wg_l[DDIM * DDIM];
__device__ __nv_bfloat16 g_w1_h[MLPD * DDIM], g_w1_l[MLPD * DDIM];
__device__ __nv_bfloat16 g_w2_h[DDIM * MLPD], g_w2_l[DDIM * MLPD];

// ======================= helpers =============================================
__device__ __forceinline__ uint32_t smem_u32(const void* p) {
    uint32_t a;
    asm("{ .reg .u64 t; cvta.to.shared.u64 t, %1; cvt.u32.u64 %0, t; }" : "=r"(a) : "l"(p));
    return a;
}
__device__ __forceinline__ void cp16(uint32_t s, const void* g) {
    asm volatile("cp.async.cg.shared.global [%0], [%1], 16;" :: "r"(s), "l"(g));
}
__device__ __forceinline__ void ldsm4(uint32_t* r, uint32_t a) {
    asm volatile("ldmatrix.sync.aligned.m8n8.x4.shared.b16 {%0,%1,%2,%3}, [%4];"
        : "=r"(r[0]), "=r"(r[1]), "=r"(r[2]), "=r"(r[3]) : "r"(a));
}
__device__ __forceinline__ void mma16816(float* d, const uint32_t* a, const uint32_t* b) {
    asm volatile("mma.sync.aligned.m16n8k16.row.col.f32.bf16.bf16.f32 "
        "{%0,%1,%2,%3}, {%4,%5,%6,%7}, {%8,%9}, {%0,%1,%2,%3};"
        : "+f"(d[0]), "+f"(d[1]), "+f"(d[2]), "+f"(d[3])
        : "r"(a[0]), "r"(a[1]), "r"(a[2]), "r"(a[3]), "r"(b[0]), "r"(b[1]));
}
__device__ __forceinline__ void split2(float v, __nv_bfloat16& h, __nv_bfloat16& l) {
    h = __float2bfloat16(v);
    l = __float2bfloat16(v - __bfloat162float(h));
}

// ================== HMMA GEMM: C[M,N] = A[M,K] @ W[K,N] ======================
// A: bf16 hi/lo row-major [M,K]. W: TRANSPOSED bf16 hi/lo row-major [N,K].
// 3-pass split: AhBh + AhBl + AlBh, fp32 register accumulation.
// 128x128x32 tiles, 4-stage cp.async pipeline, 8 warps (2m x 4n, 64x32 each).
// smem per stage: A 128x(32hi+32lo) bf16 = 16KB, B same = 32KB; 4 stages = 128KB.
// EPI: 0 = store fp32; 1 = silu(v+bias) -> bf16 hi/lo; 2 = v+bias+res -> fp32
#define STAGE_BYTES 32768
template <int EPI>
__global__ void __launch_bounds__(256, 1) mma_gemm(
    const __nv_bfloat16* __restrict__ Ah, const __nv_bfloat16* __restrict__ Al,
    const __nv_bfloat16* __restrict__ Bh, const __nv_bfloat16* __restrict__ Bl,
    float* __restrict__ Cf, __nv_bfloat16* __restrict__ Ch, __nv_bfloat16* __restrict__ Cl,
    const float* __restrict__ bias, const float* __restrict__ res,
    int M, int N, int K)
{
    extern __shared__ __align__(128) char smem[];
    const uint32_t sbase = smem_u32(smem);
    const int tid  = threadIdx.x;
    const int lane = tid & 31;
    const int wid  = tid >> 5;
    const int wm   = wid & 1;         // 0..1  -> 64-row slab
    const int wn   = wid >> 1;        // 0..3  -> 32-col slab
    const int bm = blockIdx.y * 128;
    const int bn = blockIdx.x * 128;

    // ---- cp.async geometry: 8 chunks of 16B per thread per stage -----------
    const int c8 = tid & 7;                    // 16B column within 128B row
    const int r0 = tid >> 3;                   // base row (0..31), +32*c
    const uint32_t so = (uint32_t)(c8 * 16) ^ ((uint32_t)(r0 & 7) << 4);
    const __nv_bfloat16* gA = (c8 < 4 ? Ah : Al) + (size_t)(bm + r0) * K + (c8 & 3) * 8;
    const __nv_bfloat16* gB = (c8 < 4 ? Bh : Bl) + (size_t)(bn + r0) * K + (c8 & 3) * 8;

    // ---- ldmatrix geometry ---------------------------------------------------
    const uint32_t axor = (uint32_t)(lane & 7) << 4;
    const uint32_t aRowBase = (uint32_t)(wm * 64 + (lane & 15)) * 128u;
    const uint32_t aK16 = ((lane >> 4) & 1) << 4;                 // +16B for k+8 lanes
    const uint32_t bRowBase = (uint32_t)(wn * 32 + (lane & 7) + (((lane >> 4) & 1) << 3)) * 128u;
    const uint32_t bK16 = ((lane >> 3) & 1) << 4;

    float acc[64];
    #pragma unroll
    for (int i = 0; i < 64; i++) acc[i] = 0.f;

    const int nst = K >> 5;

    // prologue: stages 0..2
    #pragma unroll
    for (int st = 0; st < 3; st++) {
        if (st < nst) {
            const uint32_t sA = sbase + (uint32_t)(st & 3) * STAGE_BYTES;
            const size_t kk = (size_t)st * 32;
            #pragma unroll
            for (int c = 0; c < 4; c++) {
                uint32_t sr = (uint32_t)(r0 + c * 32) * 128u + so;
                cp16(sA + sr, gA + kk + (size_t)c * 32 * K);
                cp16(sA + 16384 + sr, gB + kk + (size_t)c * 32 * K);
            }
        }
        asm volatile("cp.async.commit_group;" ::: "memory");
    }

    for (int it = 0; it < nst; it++) {
        const int st = it + 3;
        if (st < nst) {
            const uint32_t sA = sbase + (uint32_t)(st & 3) * STAGE_BYTES;
            const size_t kk = (size_t)st * 32;
            #pragma unroll
            for (int c = 0; c < 4; c++) {
                uint32_t sr = (uint32_t)(r0 + c * 32) * 128u + so;
                cp16(sA + sr, gA + kk + (size_t)c * 32 * K);
                cp16(sA + 16384 + sr, gB + kk + (size_t)c * 32 * K);
            }
        }
        asm volatile("cp.async.commit_group;" ::: "memory");
        asm volatile("cp.async.wait_group 3;" ::: "memory");
        __syncthreads();

        const uint32_t stoff = (uint32_t)(it & 3) * STAGE_BYTES;
        const uint32_t aB = sbase + stoff + aRowBase;
        const uint32_t bB = sbase + stoff + 16384 + bRowBase;

        #pragma unroll
        for (int s = 0; s < 2; s++) {
            const uint32_t kcH = (uint32_t)(s * 32);      // hi bytes
            const uint32_t kcL = kcH + 64;                // lo bytes
            uint32_t a[4][4], b[2][4], b2[2][4];
            // A-hi frags (4 m-tiles)
            #pragma unroll
            for (int i = 0; i < 4; i++)
                ldsm4(a[i], aB + (uint32_t)(i * 2048) + ((kcH + aK16) ^ axor));
            // B-hi frags (2 ldmatrix cover 4 n-tiles)
            #pragma unroll
            for (int j = 0; j < 2; j++)
                ldsm4(b[j], bB + (uint32_t)(j * 2048) + ((kcH + bK16) ^ axor));
            // pass 1: Ah * Bh
            #pragma unroll
            for (int i = 0; i < 4; i++)
                #pragma unroll
                for (int j = 0; j < 4; j++)
                    mma16816(&acc[(i * 4 + j) * 4], a[i], &b[j >> 1][(j & 1) * 2]);
            // B-lo frags
            #pragma unroll
            for (int j = 0; j < 2; j++)
                ldsm4(b2[j], bB + (uint32_t)(j * 2048) + ((kcL + bK16) ^ axor));
            // pass 2: Ah * Bl
            #pragma unroll
            for (int i = 0; i < 4; i++)
                #pragma unroll
                for (int j = 0; j < 4; j++)
                    mma16816(&acc[(i * 4 + j) * 4], a[i], &b2[j >> 1][(j & 1) * 2]);
            // A-lo frags (reuse a[])
            #pragma unroll
            for (int i = 0; i < 4; i++)
                ldsm4(a[i], aB + (uint32_t)(i * 2048) + ((kcL + aK16) ^ axor));
            // pass 3: Al * Bh
            #pragma unroll
            for (int i = 0; i < 4; i++)
                #pragma unroll
                for (int j = 0; j < 4; j++)
                    mma16816(&acc[(i * 4 + j) * 4], a[i], &b[j >> 1][(j & 1) * 2]);
        }
        __syncthreads();
    }

    // ---- epilogue ------------------------------------------------------------
    const int r_base = bm + wm * 64 + (lane >> 2);
    const int c_base = bn + wn * 32 + (lane & 3) * 2;
    #pragma unroll
    for (int i = 0; i < 4; i++) {
        #pragma unroll
        for (int j = 0; j < 4; j++) {
            const float* d = &acc[(i * 4 + j) * 4];
            const int col = c_base + j * 8;
            #pragma unroll
            for (int hf = 0; hf < 2; hf++) {
                const int row = r_base + i * 16 + hf * 8;
                float v0 = d[hf * 2 + 0];
                float v1 = d[hf * 2 + 1];
                const size_t off = (size_t)row * N + col;
                if (EPI == 0) {
                    *(float2*)(Cf + off) = make_float2(v0, v1);
                } else if (EPI == 1) {
                    v0 += bias[col];
                    v1 += bias[col + 1];
                    v0 = v0 / (1.0f + expf(-v0));
                    v1 = v1 / (1.0f + expf(-v1));
                    __nv_bfloat16 h0, l0, h1, l1;
                    split2(v0, h0, l0);
                    split2(v1, h1, l1);
                    *(__nv_bfloat162*)(Ch + off) = __halves2bfloat162(h0, h1);
                    *(__nv_bfloat162*)(Cl + off) = __halves2bfloat162(l0, l1);
                } else {
                    v0 += bias[col]     + res[off];
                    v1 += bias[col + 1] + res[off + 1];
                    *(float2*)(Cf + off) = make_float2(v0, v1);
                }
            }
        }
    }
}

// ================ weight prep: W[K,N] fp32 -> W^T[N,K] bf16 hi/lo ============
__global__ void prep_w(const float* __restrict__ w, __nv_bfloat16* __restrict__ hi,
                       __nv_bfloat16* __restrict__ lo, int K, int N) {
    int idx = blockIdx.x * 256 + threadIdx.x;
    if (idx >= K * N) return;
    int k = idx / N, n = idx - k * N;
    float v = w[idx];
    __nv_bfloat16 h, l;
    split2(v, h, l);
    hi[(size_t)n * K + k] = h;
    lo[(size_t)n * K + k] = l;
}

// ================ LayerNorm -> bf16 hi/lo pair ===============================
__global__ void ln_kernel(const float* __restrict__ x, const float* __restrict__ g,
                          const float* __restrict__ b,
                          __nv_bfloat16* __restrict__ yh, __nv_bfloat16* __restrict__ yl) {
    int row = blockIdx.x;
    int tid = threadIdx.x;
    const float* xr = x + (size_t)row * DDIM;
    float v0 = xr[tid], v1 = xr[tid + 256];
    float s = v0 + v1, sq = v0 * v0 + v1 * v1;
    __shared__ float rs[8], rq[8];
    #pragma unroll
    for (int o = 16; o > 0; o >>= 1) {
        s  += __shfl_down_sync(0xffffffffu, s, o);
        sq += __shfl_down_sync(0xffffffffu, sq, o);
    }
    if ((tid & 31) == 0) { rs[tid >> 5] = s; rq[tid >> 5] = sq; }
    __syncthreads();
    __shared__ float mean_s, rstd_s;
    if (tid == 0) {
        float ts = 0.f, tq = 0.f;
        #pragma unroll
        for (int i = 0; i < 8; i++) { ts += rs[i]; tq += rq[i]; }
        float m = ts * (1.0f / DDIM);
        mean_s = m; rstd_s = rsqrtf(tq * (1.0f / DDIM) - m * m + 1e-5f);
    }
    __syncthreads();
    float m = mean_s, r = rstd_s;
    size_t base = (size_t)row * DDIM;
    float o0 = (v0 - m) * r * g[tid]       + b[tid];
    float o1 = (v1 - m) * r * g[tid + 256] + b[tid + 256];
    __nv_bfloat16 h, l;
    split2(o0, h, l); yh[base + tid] = h;       yl[base + tid] = l;
    split2(o1, h, l); yh[base + tid + 256] = h; yl[base + tid + 256] = l;
}

// ====== fused: x1 = x + sigmoid(gpre+bg)*h ; xn2 = LN(x1) -> bf16 pair =======
__global__ void gate_ln_kernel(const float* __restrict__ x, const float* __restrict__ gpre,
                               const float* __restrict__ bg, const float* __restrict__ h,
                               const float* __restrict__ g2, const float* __restrict__ bn2,
                               float* __restrict__ x1,
                               __nv_bfloat16* __restrict__ yh, __nv_bfloat16* __restrict__ yl) {
    int row = blockIdx.x;
    int tid = threadIdx.x;
    size_t base = (size_t)row * DDIM;
    int c0 = tid, c1 = tid + 256;
    float gp0 = gpre[base + c0] + bg[c0];
    float gp1 = gpre[base + c1] + bg[c1];
    float v0 = x[base + c0] + (1.0f / (1.0f + expf(-gp0))) * h[base + c0];
    float v1 = x[base + c1] + (1.0f / (1.0f + expf(-gp1))) * h[base + c1];
    x1[base + c0] = v0;
    x1[base + c1] = v1;
    float s = v0 + v1, sq = v0 * v0 + v1 * v1;
    __shared__ float rs[8], rq[8];
    #pragma unroll
    for (int o = 16; o > 0; o >>= 1) {
        s  += __shfl_down_sync(0xffffffffu, s, o);
        sq += __shfl_down_sync(0xffffffffu, sq, o);
    }
    if ((tid & 31) == 0) { rs[tid >> 5] = s; rq[tid >> 5] = sq; }
    __syncthreads();
    __shared__ float mean_s, rstd_s;
    if (tid == 0) {
        float ts = 0.f, tq = 0.f;
        #pragma unroll
        for (int i = 0; i < 8; i++) { ts += rs[i]; tq += rq[i]; }
        float m = ts * (1.0f / DDIM);
        mean_s = m; rstd_s = rsqrtf(tq * (1.0f / DDIM) - m * m + 1e-5f);
    }
    __syncthreads();
    float m = mean_s, r = rstd_s;
    __nv_bfloat16 hh, ll;
    float o0 = (v0 - m) * r * g2[c0] + bn2[c0];
    float o1 = (v1 - m) * r * g2[c1] + bn2[c1];
    split2(o0, hh, ll); yh[base + c0] = hh; yl[base + c0] = ll;
    split2(o1, hh, ll); yh[base + c1] = hh; yl[base + c1] = ll;
}

// ---------------- complex linear recurrence over T ---------------------------
__global__ void scan_kernel(const float* __restrict__ beta, const float* __restrict__ log_decay,
                            const float* __restrict__ freq, float* __restrict__ craw) {
    __shared__ float s[64 * 128];
    int b = blockIdx.x;
    int tid = threadIdx.x;
    float lr = 0.f, li = 0.f, cr = 0.f, ci = 0.f;
    if (tid < 64) {
        float mag = 1.0f / (1.0f + expf(-log_decay[tid]));
        float sn, cs;
        sincosf(freq[tid], &sn, &cs);
        lr = mag * cs;
        li = mag * sn;
    }
    for (int chunk = 0; chunk < 16; chunk++) {
        size_t base = ((size_t)b * TDIM + chunk * 64) * K2;
        const float4* src = (const float4*)(beta + base);
        float4* dst = (float4*)s;
        #pragma unroll
        for (int i = 0; i < 16; i++) dst[tid + i * 128] = src[tid + i * 128];
        __syncthreads();
        if (tid < 64) {
            #pragma unroll 4
            for (int t = 0; t < 64; t++) {
                float br = s[t * 128 + tid];
                float bi = s[t * 128 + 64 + tid];
                float nr = fmaf(lr, cr, fmaf(-li, ci, br));
                float ni = fmaf(lr, ci, fmaf(li, cr, bi));
                cr = nr; ci = ni;
                s[t * 128 + tid] = cr;
                s[t * 128 + 64 + tid] = ci;
            }
        }
        __syncthreads();
        float4* out = (float4*)(craw + base);
        const float4* ssrc = (const float4*)s;
        #pragma unroll
        for (int i = 0; i < 16; i++) out[tid + i * 128] = ssrc[tid + i * 128];
        __syncthreads();
    }
}

// -------- per-head coupling -> eig fp32 (output) + bf16 hi/lo pair -----------
__global__ void coupling_kernel(const float* __restrict__ craw, const float* __restrict__ coup,
                                float* __restrict__ eig,
                                __nv_bfloat16* __restrict__ eh, __nv_bfloat16* __restrict__ el) {
    __shared__ float sc[HDIM * KPD * KPD];
    __shared__ float row[4 * K2];
    int tid = threadIdx.x;
    #pragma unroll
    for (int i = tid; i < HDIM * KPD * KPD; i += 256) sc[i] = coup[i];
    const float2* src = (const float2*)(craw + (size_t)blockIdx.x * 4 * K2);
    ((float2*)row)[tid] = src[tid];
    __syncthreads();
    int local = tid >> 6;
    int j = tid & 63;
    int h = j >> 4, jj = j & 15;
    const float* cp = &sc[h * 256 + jj * 16];
    const float* rr = &row[local * K2 + h * 16];
    float accr = 0.f, acci = 0.f;
    #pragma unroll
    for (int k = 0; k < 16; k++) {
        accr = fmaf(cp[k], rr[k], accr);
        acci = fmaf(cp[k], rr[k + 64], acci);
    }
    size_t token = (size_t)blockIdx.x * 4 + local;
    eig[token * K2 + j] = accr;
    eig[token * K2 + 64 + j] = acci;
    __nv_bfloat16 hh, ll;
    split2(accr, hh, ll); eh[token * K2 + j] = hh;      el[token * K2 + j] = ll;
    split2(acci, hh, ll); eh[token * K2 + 64 + j] = hh; el[token * K2 + 64 + j] = ll;
}

// =============================================================================
extern "C" void kernel_launch(void* const* d_in, const int* in_sizes, int n_in,
                              void* d_out, int out_size) {
    const float* x         = (const float*)d_in[0];
    const float* w_in      = (const float*)d_in[1];
    const float* log_decay = (const float*)d_in[2];
    const float* frequency = (const float*)d_in[3];
    const float* coupling  = (const float*)d_in[4];
    const float* w_out     = (const float*)d_in[5];
    const float* w_gate    = (const float*)d_in[6];
    const float* b_gate    = (const float*)d_in[7];
    const float* w1        = (const float*)d_in[8];
    const float* b1        = (const float*)d_in[9];
    const float* w2        = (const float*)d_in[10];
    const float* b2        = (const float*)d_in[11];
    const float* g1        = (const float*)d_in[12];
    const float* bn1       = (const float*)d_in[13];
    const float* g2        = (const float*)d_in[14];
    const float* bn2       = (const float*)d_in[15];

    float* out = (float*)d_out;
    float* eig = out + (size_t)BT * DDIM;

    float *beta, *craw, *gpre, *hbuf, *x1;
    __nv_bfloat16 *xnh, *xnl, *xn2h, *xn2l, *eh, *el, *t1h, *t1l;
    __nv_bfloat16 *wih, *wil, *woh, *wol, *wgh, *wgl, *w1h, *w1l, *w2h, *w2l;
    cudaGetSymbolAddress((void**)&beta, g_beta);
    cudaGetSymbolAddress((void**)&craw, g_craw);
    cudaGetSymbolAddress((void**)&gpre, g_gpre);
    cudaGetSymbolAddress((void**)&hbuf, g_h);
    cudaGetSymbolAddress((void**)&x1,   g_x1);
    cudaGetSymbolAddress((void**)&xnh,  g_xn_h);  cudaGetSymbolAddress((void**)&xnl,  g_xn_l);
    cudaGetSymbolAddress((void**)&xn2h, g_xn2_h); cudaGetSymbolAddress((void**)&xn2l, g_xn2_l);
    cudaGetSymbolAddress((void**)&eh,   g_eig_h); cudaGetSymbolAddress((void**)&el,   g_eig_l);
    cudaGetSymbolAddress((void**)&t1h,  g_t1_h);  cudaGetSymbolAddress((void**)&t1l,  g_t1_l);
    cudaGetSymbolAddress((void**)&wih,  g_wi_h);  cudaGetSymbolAddress((void**)&wil,  g_wi_l);
    cudaGetSymbolAddress((void**)&woh,  g_wo_h);  cudaGetSymbolAddress((void**)&wol,  g_wo_l);
    cudaGetSymbolAddress((void**)&wgh,  g_wg_h);  cudaGetSymbolAddress((void**)&wgl,  g_wg_l);
    cudaGetSymbolAddress((void**)&w1h,  g_w1_h);  cudaGetSymbolAddress((void**)&w1l,  g_w1_l);
    cudaGetSymbolAddress((void**)&w2h,  g_w2_h);  cudaGetSymbolAddress((void**)&w2l,  g_w2_l);

    const int SMEM = 4 * STAGE_BYTES;   // 128 KB
    cudaFuncSetAttribute(mma_gemm<0>, cudaFuncAttributeMaxDynamicSharedMemorySize, SMEM);
    cudaFuncSetAttribute(mma_gemm<1>, cudaFuncAttributeMaxDynamicSharedMemorySize, SMEM);
    cudaFuncSetAttribute(mma_gemm<2>, cudaFuncAttributeMaxDynamicSharedMemorySize, SMEM);

    // weight prep (transpose + bf16 hi/lo split)
    prep_w<<<(DDIM * K2   + 255) / 256, 256>>>(w_in,   wih, wil, DDIM, K2);
    prep_w<<<(K2 * DDIM   + 255) / 256, 256>>>(w_out,  woh, wol, K2,   DDIM);
    prep_w<<<(DDIM * DDIM + 255) / 256, 256>>>(w_gate, wgh, wgl, DDIM, DDIM);
    prep_w<<<(DDIM * MLPD + 255) / 256, 256>>>(w1,     w1h, w1l, DDIM, MLPD);
    prep_w<<<(MLPD * DDIM + 255) / 256, 256>>>(w2,     w2h, w2l, MLPD, DDIM);

    // 1. xn = LN(x) -> bf16 pair
    ln_kernel<<<BT, 256>>>(x, g1, bn1, xnh, xnl);
    // 2. beta = xn @ w_in   [BT,512]x[512,128]
    mma_gemm<0><<<dim3(1, BT / 128), 256, SMEM>>>(xnh, xnl, wih, wil, beta, nullptr, nullptr, nullptr, nullptr, BT, K2, DDIM);
    // 3. complex causal recurrence
    scan_kernel<<<BDIM, 128>>>(beta, log_decay, frequency, craw);
    // 4. coupling -> eigenstates (output) + bf16 pair
    coupling_kernel<<<BT / 4, 256>>>(craw, coupling, eig, eh, el);
    // 5. h = eig @ w_out   [BT,128]x[128,512]
    mma_gemm<0><<<dim3(DDIM / 128, BT / 128), 256, SMEM>>>(eh, el, woh, wol, hbuf, nullptr, nullptr, nullptr, nullptr, BT, DDIM, K2);
    // 6. gpre = xn @ w_gate [BT,512]x[512,512]
    mma_gemm<0><<<dim3(DDIM / 128, BT / 128), 256, SMEM>>>(xnh, xnl, wgh, wgl, gpre, nullptr, nullptr, nullptr, nullptr, BT, DDIM, DDIM);
    // 7. x1 = x + sigmoid(gpre+bg)*h ; xn2 = LN(x1) -> bf16 pair
    gate_ln_kernel<<<BT, 256>>>(x, gpre, b_gate, hbuf, g2, bn2, x1, xn2h, xn2l);
    // 8. t1 = silu(xn2 @ w1 + b1) -> bf16 pair   [BT,512]x[512,2048]
    mma_gemm<1><<<dim3(MLPD / 128, BT / 128), 256, SMEM>>>(xn2h, xn2l, w1h, w1l, nullptr, t1h, t1l, b1, nullptr, BT, MLPD, DDIM);
    // 9. out = x1 + t1 @ w2 + b2   [BT,2048]x[2048,512]
    mma_gemm<2><<<dim3(DDIM / 128, BT / 128), 256, SMEM>>>(t1h, t1l, w2h, w2l, out, nullptr, nullptr, b2, x1, BT, DDIM, MLPD);
}

// round 4
// speedup vs baseline: 3.7578x; 1.4952x over previous
#include <cuda_runtime.h>
#include <cuda_fp16.h>
#include <math.h>
#include <stdint.h>

#define BDIM 32
#define TDIM 1024
#define DDIM 512
#define K2   128
#define HDIM 4
#define KPD  16
#define MLPD 2048
#define BT   (BDIM * TDIM)

// ---------------- scratch (static device arrays; no allocation) -------------
__device__ float g_beta[(size_t)BT * K2];
__device__ float g_craw[(size_t)BT * K2];
__device__ float g_gpre[(size_t)BT * DDIM];
__device__ float g_h   [(size_t)BT * DDIM];
__device__ float g_x1  [(size_t)BT * DDIM];
__device__ __half g_xn_h [(size_t)BT * DDIM];
__device__ __half g_xn2_h[(size_t)BT * DDIM];
__device__ __half g_eig_h[(size_t)BT * K2];
__device__ __half g_t1_h [(size_t)BT * MLPD];
// transposed weights [N, K] as fp16 hi/lo
__device__ __half g_wc_h[(K2 + DDIM) * DDIM], g_wc_l[(K2 + DDIM) * DDIM];  // concat w_in^T | w_gate^T
__device__ __half g_wo_h[DDIM * K2],   g_wo_l[DDIM * K2];
__device__ __half g_w1_h[MLPD * DDIM], g_w1_l[MLPD * DDIM];
__device__ __half g_w2_h[DDIM * MLPD], g_w2_l[DDIM * MLPD];

// ======================= helpers =============================================
__device__ __forceinline__ uint32_t smem_u32(const void* p) {
    uint32_t a;
    asm("{ .reg .u64 t; cvta.to.shared.u64 t, %1; cvt.u32.u64 %0, t; }" : "=r"(a) : "l"(p));
    return a;
}
__device__ __forceinline__ void cp16(uint32_t s, const void* g) {
    asm volatile("cp.async.cg.shared.global [%0], [%1], 16;" :: "r"(s), "l"(g));
}
__device__ __forceinline__ void ldsm4(uint32_t* r, uint32_t a) {
    asm volatile("ldmatrix.sync.aligned.m8n8.x4.shared.b16 {%0,%1,%2,%3}, [%4];"
        : "=r"(r[0]), "=r"(r[1]), "=r"(r[2]), "=r"(r[3]) : "r"(a));
}
__device__ __forceinline__ void mma16816(float* d, const uint32_t* a, const uint32_t* b) {
    asm volatile("mma.sync.aligned.m16n8k16.row.col.f32.f16.f16.f32 "
        "{%0,%1,%2,%3}, {%4,%5,%6,%7}, {%8,%9}, {%0,%1,%2,%3};"
        : "+f"(d[0]), "+f"(d[1]), "+f"(d[2]), "+f"(d[3])
        : "r"(a[0]), "r"(a[1]), "r"(a[2]), "r"(a[3]), "r"(b[0]), "r"(b[1]));
}

// ================== HMMA GEMM: C[M,N] = A[M,K] @ W[K,N] ======================
// A: fp16 row-major [M,K]. W: TRANSPOSED fp16 hi/lo row-major [N,K].
// 2-pass split: Ah*Bh + Ah*Bl, fp32 register accumulation.
// 128x128x64 tiles, 4-stage cp.async pipeline, 8 warps (2m x 4n, 64x32 each).
// Stage: A 16KB + Bh 16KB + Bl 16KB = 48KB; 4 stages = 192KB smem.
// EPI: 0 = fp32 store; 1 = silu(v+bias) -> fp16; 2 = v+bias+res -> fp32;
//      3 = split store: blockIdx.x==0 -> Cf2 (width 128), else Cf (width 512)
#define STAGE_BYTES 49152
template <int EPI>
__global__ void __launch_bounds__(256, 1) mma_gemm(
    const __half* __restrict__ Ah,
    const __half* __restrict__ Bh, const __half* __restrict__ Bl,
    float* __restrict__ Cf, __half* __restrict__ Ch,
    const float* __restrict__ bias, const float* __restrict__ res,
    float* __restrict__ Cf2,
    int M, int N, int K)
{
    extern __shared__ __align__(128) char smem[];
    const uint32_t sbase = smem_u32(smem);
    const int tid  = threadIdx.x;
    const int lane = tid & 31;
    const int wid  = tid >> 5;
    const int wm   = wid & 1;
    const int wn   = wid >> 1;
    const int bm = blockIdx.y * 128;
    const int bn = blockIdx.x * 128;

    // cp.async geometry: rows of 128B (64 fp16)
    const int c8 = tid & 7;
    const int r0 = tid >> 3;
    const uint32_t so = (uint32_t)(c8 * 16) ^ ((uint32_t)(r0 & 7) << 4);
    const __half* gA  = Ah + (size_t)(bm + r0) * K + c8 * 8;
    const __half* gBh = Bh + (size_t)(bn + r0) * K + c8 * 8;
    const __half* gBl = Bl + (size_t)(bn + r0) * K + c8 * 8;

    // ldmatrix geometry
    const uint32_t axor = (uint32_t)(lane & 7) << 4;
    const uint32_t aRowBase = (uint32_t)(wm * 64 + (lane & 15)) * 128u;
    const uint32_t aK16 = ((lane >> 4) & 1) << 4;
    const uint32_t bRowBase = (uint32_t)(wn * 32 + (lane & 7) + (((lane >> 4) & 1) << 3)) * 128u;
    const uint32_t bK16 = ((lane >> 3) & 1) << 4;

    float acc[64];
    #pragma unroll
    for (int i = 0; i < 64; i++) acc[i] = 0.f;

    const int nst = K >> 6;      // chunks of 64

    #pragma unroll
    for (int st = 0; st < 3; st++) {
        if (st < nst) {
            const uint32_t sb = sbase + (uint32_t)(st & 3) * STAGE_BYTES;
            const size_t kk = (size_t)st * 64;
            #pragma unroll
            for (int c = 0; c < 4; c++) {
                uint32_t sr = (uint32_t)(r0 + c * 32) * 128u + so;
                const size_t go = kk + (size_t)c * 32 * K;
                cp16(sb + sr,         gA  + go);
                cp16(sb + 16384 + sr, gBh + go);
                cp16(sb + 32768 + sr, gBl + go);
            }
        }
        asm volatile("cp.async.commit_group;" ::: "memory");
    }

    for (int it = 0; it < nst; it++) {
        const int st = it + 3;
        if (st < nst) {
            const uint32_t sb = sbase + (uint32_t)(st & 3) * STAGE_BYTES;
            const size_t kk = (size_t)st * 64;
            #pragma unroll
            for (int c = 0; c < 4; c++) {
                uint32_t sr = (uint32_t)(r0 + c * 32) * 128u + so;
                const size_t go = kk + (size_t)c * 32 * K;
                cp16(sb + sr,         gA  + go);
                cp16(sb + 16384 + sr, gBh + go);
                cp16(sb + 32768 + sr, gBl + go);
            }
        }
        asm volatile("cp.async.commit_group;" ::: "memory");
        asm volatile("cp.async.wait_group 3;" ::: "memory");
        __syncthreads();

        const uint32_t stoff = (uint32_t)(it & 3) * STAGE_BYTES;
        const uint32_t aB  = sbase + stoff + aRowBase;
        const uint32_t bBh = sbase + stoff + 16384 + bRowBase;
        const uint32_t bBl = sbase + stoff + 32768 + bRowBase;

        #pragma unroll
        for (int s = 0; s < 4; s++) {
            const uint32_t kc = (uint32_t)(s * 32);     // 16 halves = 32B per step
            uint32_t a[4][4], b[2][4], b2[2][4];
            #pragma unroll
            for (int i = 0; i < 4; i++)
                ldsm4(a[i], aB + (uint32_t)(i * 2048) + ((kc + aK16) ^ axor));
            #pragma unroll
            for (int j = 0; j < 2; j++)
                ldsm4(b[j], bBh + (uint32_t)(j * 2048) + ((kc + bK16) ^ axor));
            #pragma unroll
            for (int i = 0; i < 4; i++)
                #pragma unroll
                for (int j = 0; j < 4; j++)
                    mma16816(&acc[(i * 4 + j) * 4], a[i], &b[j >> 1][(j & 1) * 2]);
            #pragma unroll
            for (int j = 0; j < 2; j++)
                ldsm4(b2[j], bBl + (uint32_t)(j * 2048) + ((kc + bK16) ^ axor));
            #pragma unroll
            for (int i = 0; i < 4; i++)
                #pragma unroll
                for (int j = 0; j < 4; j++)
                    mma16816(&acc[(i * 4 + j) * 4], a[i], &b2[j >> 1][(j & 1) * 2]);
        }
        __syncthreads();
    }

    // ---- epilogue ------------------------------------------------------------
    const int r_base = bm + wm * 64 + (lane >> 2);
    const int c_base = bn + wn * 32 + (lane & 3) * 2;
    #pragma unroll
    for (int i = 0; i < 4; i++) {
        #pragma unroll
        for (int j = 0; j < 4; j++) {
            const float* d = &acc[(i * 4 + j) * 4];
            const int col = c_base + j * 8;
            #pragma unroll
            for (int hf = 0; hf < 2; hf++) {
                const int row = r_base + i * 16 + hf * 8;
                float v0 = d[hf * 2 + 0];
                float v1 = d[hf * 2 + 1];
                if (EPI == 0) {
                    *(float2*)(Cf + (size_t)row * N + col) = make_float2(v0, v1);
                } else if (EPI == 1) {
                    const size_t off = (size_t)row * N + col;
                    v0 += bias[col];
                    v1 += bias[col + 1];
                    v0 = v0 / (1.0f + expf(-v0));
                    v1 = v1 / (1.0f + expf(-v1));
                    *(__half2*)(Ch + off) = __floats2half2_rn(v0, v1);
                } else if (EPI == 2) {
                    const size_t off = (size_t)row * N + col;
                    v0 += bias[col]     + res[off];
                    v1 += bias[col + 1] + res[off + 1];
                    *(float2*)(Cf + off) = make_float2(v0, v1);
                } else {
                    if (blockIdx.x == 0)
                        *(float2*)(Cf2 + (size_t)row * K2 + col) = make_float2(v0, v1);
                    else
                        *(float2*)(Cf + (size_t)row * DDIM + (col - K2)) = make_float2(v0, v1);
                }
            }
        }
    }
}

// ====== weight prep: W[K,N] fp32 -> W^T[N,K] fp16 hi/lo, tiled transpose =====
__global__ void prep_w_t(const float* __restrict__ w, __half* __restrict__ hi,
                         __half* __restrict__ lo, int K, int N) {
    __shared__ float tile[32][33];
    const int k0 = blockIdx.x * 32;
    const int n0 = blockIdx.y * 32;
    const int tx = threadIdx.x, ty = threadIdx.y;
    #pragma unroll
    for (int i = ty; i < 32; i += 8)
        tile[i][tx] = w[(size_t)(k0 + i) * N + n0 + tx];
    __syncthreads();
    #pragma unroll
    for (int i = ty; i < 32; i += 8) {
        float v = tile[tx][n0 + i - n0];   // tile[tx][i]
        v = tile[tx][i];
        __half h = __float2half_rn(v);
        __half l = __float2half_rn(v - __half2float(h));
        hi[(size_t)(n0 + i) * K + k0 + tx] = h;
        lo[(size_t)(n0 + i) * K + k0 + tx] = l;
    }
}

// ================ LayerNorm -> fp16 ==========================================
__global__ void ln_kernel(const float* __restrict__ x, const float* __restrict__ g,
                          const float* __restrict__ b, __half* __restrict__ y) {
    int row = blockIdx.x;
    int tid = threadIdx.x;
    const float* xr = x + (size_t)row * DDIM;
    float v0 = xr[tid], v1 = xr[tid + 256];
    float s = v0 + v1, sq = v0 * v0 + v1 * v1;
    __shared__ float rs[8], rq[8];
    #pragma unroll
    for (int o = 16; o > 0; o >>= 1) {
        s  += __shfl_down_sync(0xffffffffu, s, o);
        sq += __shfl_down_sync(0xffffffffu, sq, o);
    }
    if ((tid & 31) == 0) { rs[tid >> 5] = s; rq[tid >> 5] = sq; }
    __syncthreads();
    __shared__ float mean_s, rstd_s;
    if (tid == 0) {
        float ts = 0.f, tq = 0.f;
        #pragma unroll
        for (int i = 0; i < 8; i++) { ts += rs[i]; tq += rq[i]; }
        float m = ts * (1.0f / DDIM);
        mean_s = m; rstd_s = rsqrtf(tq * (1.0f / DDIM) - m * m + 1e-5f);
    }
    __syncthreads();
    float m = mean_s, r = rstd_s;
    size_t base = (size_t)row * DDIM;
    y[base + tid]       = __float2half_rn((v0 - m) * r * g[tid]       + b[tid]);
    y[base + tid + 256] = __float2half_rn((v1 - m) * r * g[tid + 256] + b[tid + 256]);
}

// ====== fused: x1 = x + sigmoid(gpre+bg)*h ; xn2 = LN(x1) -> fp16 ============
__global__ void gate_ln_kernel(const float* __restrict__ x, const float* __restrict__ gpre,
                               const float* __restrict__ bg, const float* __restrict__ h,
                               const float* __restrict__ g2, const float* __restrict__ bn2,
                               float* __restrict__ x1, __half* __restrict__ y) {
    int row = blockIdx.x;
    int tid = threadIdx.x;
    size_t base = (size_t)row * DDIM;
    int c0 = tid, c1 = tid + 256;
    float gp0 = gpre[base + c0] + bg[c0];
    float gp1 = gpre[base + c1] + bg[c1];
    float v0 = x[base + c0] + (1.0f / (1.0f + expf(-gp0))) * h[base + c0];
    float v1 = x[base + c1] + (1.0f / (1.0f + expf(-gp1))) * h[base + c1];
    x1[base + c0] = v0;
    x1[base + c1] = v1;
    float s = v0 + v1, sq = v0 * v0 + v1 * v1;
    __shared__ float rs[8], rq[8];
    #pragma unroll
    for (int o = 16; o > 0; o >>= 1) {
        s  += __shfl_down_sync(0xffffffffu, s, o);
        sq += __shfl_down_sync(0xffffffffu, sq, o);
    }
    if ((tid & 31) == 0) { rs[tid >> 5] = s; rq[tid >> 5] = sq; }
    __syncthreads();
    __shared__ float mean_s, rstd_s;
    if (tid == 0) {
        float ts = 0.f, tq = 0.f;
        #pragma unroll
        for (int i = 0; i < 8; i++) { ts += rs[i]; tq += rq[i]; }
        float m = ts * (1.0f / DDIM);
        mean_s = m; rstd_s = rsqrtf(tq * (1.0f / DDIM) - m * m + 1e-5f);
    }
    __syncthreads();
    float m = mean_s, r = rstd_s;
    y[base + c0] = __float2half_rn((v0 - m) * r * g2[c0] + bn2[c0]);
    y[base + c1] = __float2half_rn((v1 - m) * r * g2[c1] + bn2[c1]);
}

// ------------- parallel complex linear recurrence (3-phase chunked scan) -----
// grid = B (32), block = 1024 = 16 chunks x 64 modes.
__global__ void __launch_bounds__(1024, 1) scan_kernel(
    const float* __restrict__ beta, const float* __restrict__ log_decay,
    const float* __restrict__ freq, float* __restrict__ craw)
{
    __shared__ float carr_r[16 * 64], carr_i[16 * 64];
    __shared__ float pref_r[16 * 64], pref_i[16 * 64];
    const int b  = blockIdx.x;
    const int tid = threadIdx.x;
    const int ch = tid >> 6;            // 0..15
    const int k  = tid & 63;            // mode

    float mag = 1.0f / (1.0f + expf(-log_decay[k]));
    float sn, cs;
    sincosf(freq[k], &sn, &cs);
    const float lr = mag * cs, li = mag * sn;

    // lambda^64 by 6 squarings
    float pr = lr, pi = li;
    #pragma unroll
    for (int q = 0; q < 6; q++) {
        float nr = pr * pr - pi * pi;
        float ni = 2.f * pr * pi;
        pr = nr; pi = ni;
    }

    // phase A: local scan (zero initial state)
    const size_t tok0 = (size_t)b * TDIM + ch * 64;
    float cr = 0.f, ci = 0.f;
    for (int i = 0; i < 64; i++) {
        const size_t o = (tok0 + i) * K2;
        float br = beta[o + k];
        float bi = beta[o + 64 + k];
        float nr = fmaf(lr, cr, fmaf(-li, ci, br));
        float ni = fmaf(lr, ci, fmaf(li, cr, bi));
        cr = nr; ci = ni;
        craw[o + k] = cr;
        craw[o + 64 + k] = ci;
    }
    carr_r[ch * 64 + k] = cr;
    carr_i[ch * 64 + k] = ci;
    __syncthreads();

    // phase B: serial carry combine (64 threads)
    if (tid < 64) {
        float sr = 0.f, si = 0.f;
        #pragma unroll
        for (int j = 0; j < 16; j++) {
            pref_r[j * 64 + k] = sr;
            pref_i[j * 64 + k] = si;
            float nr = carr_r[j * 64 + k] + pr * sr - pi * si;
            float ni = carr_i[j * 64 + k] + pr * si + pi * sr;
            sr = nr; si = ni;
        }
    }
    __syncthreads();

    // phase C: add carry * lambda^(i+1)
    if (ch > 0) {
        float sr = pref_r[ch * 64 + k];
        float si = pref_i[ch * 64 + k];
        if (sr != 0.f || si != 0.f) {
            float fr = lr, fi = li;
            for (int i = 0; i < 64; i++) {
                const size_t o = (tok0 + i) * K2;
                float addr_ = fr * sr - fi * si;
                float addi_ = fr * si + fi * sr;
                craw[o + k]      += addr_;
                craw[o + 64 + k] += addi_;
                float nr = fr * lr - fi * li;
                float ni = fr * li + fi * lr;
                fr = nr; fi = ni;
            }
        }
    }
}

// -------- per-head coupling -> eig fp32 (output) + fp16 ---------------------
__global__ void coupling_kernel(const float* __restrict__ craw, const float* __restrict__ coup,
                                float* __restrict__ eig, __half* __restrict__ eh) {
    __shared__ float sc[HDIM * KPD * KPD];
    __shared__ float row[4 * K2];
    int tid = threadIdx.x;
    #pragma unroll
    for (int i = tid; i < HDIM * KPD * KPD; i += 256) sc[i] = coup[i];
    const float2* src = (const float2*)(craw + (size_t)blockIdx.x * 4 * K2);
    ((float2*)row)[tid] = src[tid];
    __syncthreads();
    int local = tid >> 6;
    int j = tid & 63;
    int h = j >> 4, jj = j & 15;
    const float* cp = &sc[h * 256 + jj * 16];
    const float* rr = &row[local * K2 + h * 16];
    float accr = 0.f, acci = 0.f;
    #pragma unroll
    for (int k = 0; k < 16; k++) {
        accr = fmaf(cp[k], rr[k], accr);
        acci = fmaf(cp[k], rr[k + 64], acci);
    }
    size_t token = (size_t)blockIdx.x * 4 + local;
    eig[token * K2 + j] = accr;
    eig[token * K2 + 64 + j] = acci;
    eh[token * K2 + j]      = __float2half_rn(accr);
    eh[token * K2 + 64 + j] = __float2half_rn(acci);
}

// =============================================================================
extern "C" void kernel_launch(void* const* d_in, const int* in_sizes, int n_in,
                              void* d_out, int out_size) {
    const float* x         = (const float*)d_in[0];
    const float* w_in      = (const float*)d_in[1];
    const float* log_decay = (const float*)d_in[2];
    const float* frequency = (const float*)d_in[3];
    const float* coupling  = (const float*)d_in[4];
    const float* w_out     = (const float*)d_in[5];
    const float* w_gate    = (const float*)d_in[6];
    const float* b_gate    = (const float*)d_in[7];
    const float* w1        = (const float*)d_in[8];
    const float* b1        = (const float*)d_in[9];
    const float* w2        = (const float*)d_in[10];
    const float* b2        = (const float*)d_in[11];
    const float* g1        = (const float*)d_in[12];
    const float* bn1       = (const float*)d_in[13];
    const float* g2        = (const float*)d_in[14];
    const float* bn2       = (const float*)d_in[15];

    float* out = (float*)d_out;
    float* eig = out + (size_t)BT * DDIM;

    float *beta, *craw, *gpre, *hbuf, *x1;
    __half *xnh, *xn2h, *eh, *t1h;
    __half *wch, *wcl, *woh, *wol, *w1h, *w1l, *w2h, *w2l;
    cudaGetSymbolAddress((void**)&beta, g_beta);
    cudaGetSymbolAddress((void**)&craw, g_craw);
    cudaGetSymbolAddress((void**)&gpre, g_gpre);
    cudaGetSymbolAddress((void**)&hbuf, g_h);
    cudaGetSymbolAddress((void**)&x1,   g_x1);
    cudaGetSymbolAddress((void**)&xnh,  g_xn_h);
    cudaGetSymbolAddress((void**)&xn2h, g_xn2_h);
    cudaGetSymbolAddress((void**)&eh,   g_eig_h);
    cudaGetSymbolAddress((void**)&t1h,  g_t1_h);
    cudaGetSymbolAddress((void**)&wch,  g_wc_h);  cudaGetSymbolAddress((void**)&wcl,  g_wc_l);
    cudaGetSymbolAddress((void**)&woh,  g_wo_h);  cudaGetSymbolAddress((void**)&wol,  g_wo_l);
    cudaGetSymbolAddress((void**)&w1h,  g_w1_h);  cudaGetSymbolAddress((void**)&w1l,  g_w1_l);
    cudaGetSymbolAddress((void**)&w2h,  g_w2_h);  cudaGetSymbolAddress((void**)&w2l,  g_w2_l);

    const int SMEM = 4 * STAGE_BYTES;   // 192 KB
    cudaFuncSetAttribute(mma_gemm<0>, cudaFuncAttributeMaxDynamicSharedMemorySize, SMEM);
    cudaFuncSetAttribute(mma_gemm<1>, cudaFuncAttributeMaxDynamicSharedMemorySize, SMEM);
    cudaFuncSetAttribute(mma_gemm<2>, cudaFuncAttributeMaxDynamicSharedMemorySize, SMEM);
    cudaFuncSetAttribute(mma_gemm<3>, cudaFuncAttributeMaxDynamicSharedMemorySize, SMEM);

    // weight prep: tiled transpose + fp16 hi/lo split
    dim3 tb(32, 8);
    prep_w_t<<<dim3(DDIM / 32, K2 / 32),   tb>>>(w_in,   wch,              wcl,              DDIM, K2);
    prep_w_t<<<dim3(DDIM / 32, DDIM / 32), tb>>>(w_gate, wch + K2 * DDIM,  wcl + K2 * DDIM,  DDIM, DDIM);
    prep_w_t<<<dim3(K2 / 32,   DDIM / 32), tb>>>(w_out,  woh,              wol,              K2,   DDIM);
    prep_w_t<<<dim3(DDIM / 32, MLPD / 32), tb>>>(w1,     w1h,              w1l,              DDIM, MLPD);
    prep_w_t<<<dim3(MLPD / 32, DDIM / 32), tb>>>(w2,     w2h,              w2l,              MLPD, DDIM);

    // 1. xn = LN(x) -> fp16
    ln_kernel<<<BT, 256>>>(x, g1, bn1, xnh);
    // 2+6 merged: [beta | gpre] = xn @ [w_in | w_gate]   N=640
    mma_gemm<3><<<dim3((K2 + DDIM) / 128, BT / 128), 256, SMEM>>>(
        xnh, wch, wcl, gpre, nullptr, nullptr, nullptr, beta, BT, K2 + DDIM, DDIM);
    // 3. parallel chunked complex recurrence
    scan_kernel<<<BDIM, 1024>>>(beta, log_decay, frequency, craw);
    // 4. coupling -> eigenstates (output) + fp16
    coupling_kernel<<<BT / 4, 256>>>(craw, coupling, eig, eh);
    // 5. h = eig @ w_out   [BT,128]x[128,512]
    mma_gemm<0><<<dim3(DDIM / 128, BT / 128), 256, SMEM>>>(
        eh, woh, wol, hbuf, nullptr, nullptr, nullptr, nullptr, BT, DDIM, K2);
    // 7. x1 = x + sigmoid(gpre+bg)*h ; xn2 = LN(x1) -> fp16
    gate_ln_kernel<<<BT, 256>>>(x, gpre, b_gate, hbuf, g2, bn2, x1, xn2h);
    // 8. t1 = silu(xn2 @ w1 + b1) -> fp16   [BT,512]x[512,2048]
    mma_gemm<1><<<dim3(MLPD / 128, BT / 128), 256, SMEM>>>(
        xn2h, w1h, w1l, nullptr, t1h, b1, nullptr, nullptr, BT, MLPD, DDIM);
    // 9. out = x1 + t1 @ w2 + b2   [BT,2048]x[2048,512]
    mma_gemm<2><<<dim3(DDIM / 128, BT / 128), 256, SMEM>>>(
        t1h, w2h, w2l, out, nullptr, b2, x1, nullptr, BT, DDIM, MLPD);
}

// round 5
// speedup vs baseline: 5.1476x; 1.3699x over previous
#include <cuda_runtime.h>
#include <cuda_fp16.h>
#include <math.h>
#include <stdint.h>

#define BDIM 32
#define TDIM 1024
#define DDIM 512
#define K2   128
#define HDIM 4
#define KPD  16
#define MLPD 2048
#define BT   (BDIM * TDIM)

// ---------------- scratch (static device arrays; no allocation) -------------
__device__ float g_beta[(size_t)BT * K2];
__device__ float g_craw[(size_t)BT * K2];
__device__ float g_h   [(size_t)BT * DDIM];
__device__ float g_x1  [(size_t)BT * DDIM];
__device__ __half g_gate [(size_t)BT * DDIM];
__device__ __half g_xn_h [(size_t)BT * DDIM];
__device__ __half g_xn2_h[(size_t)BT * DDIM];
__device__ __half g_eig_h[(size_t)BT * K2];
__device__ __half g_t1_h [(size_t)BT * MLPD];
// transposed weights [N, K] as fp16
__device__ __half g_wc_h[(K2 + DDIM) * DDIM];   // concat w_in^T | w_gate^T
__device__ __half g_wo_h[DDIM * K2];
__device__ __half g_w1_h[MLPD * DDIM];
__device__ __half g_w2_h[DDIM * MLPD];

// ======================= helpers =============================================
__device__ __forceinline__ uint32_t smem_u32(const void* p) {
    uint32_t a;
    asm("{ .reg .u64 t; cvta.to.shared.u64 t, %1; cvt.u32.u64 %0, t; }" : "=r"(a) : "l"(p));
    return a;
}
__device__ __forceinline__ void cp16(uint32_t s, const void* g) {
    asm volatile("cp.async.cg.shared.global [%0], [%1], 16;" :: "r"(s), "l"(g));
}
__device__ __forceinline__ void ldsm4(uint32_t* r, uint32_t a) {
    asm volatile("ldmatrix.sync.aligned.m8n8.x4.shared.b16 {%0,%1,%2,%3}, [%4];"
        : "=r"(r[0]), "=r"(r[1]), "=r"(r[2]), "=r"(r[3]) : "r"(a));
}
__device__ __forceinline__ void mma16816(float* d, const uint32_t* a, const uint32_t* b) {
    asm volatile("mma.sync.aligned.m16n8k16.row.col.f32.f16.f16.f32 "
        "{%0,%1,%2,%3}, {%4,%5,%6,%7}, {%8,%9}, {%0,%1,%2,%3};"
        : "+f"(d[0]), "+f"(d[1]), "+f"(d[2]), "+f"(d[3])
        : "r"(a[0]), "r"(a[1]), "r"(a[2]), "r"(a[3]), "r"(b[0]), "r"(b[1]));
}

// ================== HMMA GEMM: C[M,N] = A[M,K] @ W[K,N] ======================
// A: fp16 row-major [M,K]. W: TRANSPOSED fp16 row-major [N,K]. Single pass.
// 128x128x64 tiles, 4-stage cp.async pipeline, 8 warps (2m x 4n, 64x32 each).
// Stage: A 16KB + B 16KB = 32KB; 4 stages = 128KB smem.
// EPI: 0 = fp32 store; 1 = silu(v+bias) -> fp16; 2 = v+bias+res -> fp32;
//      3 = split: blockIdx.x==0 -> Cf2 fp32 (width 128),
//                 else sigmoid(v + bias[col-128]) -> Ch fp16 (width 512)
#define STAGE_BYTES 32768
template <int EPI>
__global__ void __launch_bounds__(256, 1) mma_gemm(
    const __half* __restrict__ Ah,
    const __half* __restrict__ Bh,
    float* __restrict__ Cf, __half* __restrict__ Ch,
    const float* __restrict__ bias, const float* __restrict__ res,
    float* __restrict__ Cf2,
    int M, int N, int K)
{
    extern __shared__ __align__(128) char smem[];
    const uint32_t sbase = smem_u32(smem);
    const int tid  = threadIdx.x;
    const int lane = tid & 31;
    const int wid  = tid >> 5;
    const int wm   = wid & 1;
    const int wn   = wid >> 1;
    const int bm = blockIdx.y * 128;
    const int bn = blockIdx.x * 128;

    // cp.async geometry: rows of 128B (64 fp16)
    const int c8 = tid & 7;
    const int r0 = tid >> 3;
    const uint32_t so = (uint32_t)(c8 * 16) ^ ((uint32_t)(r0 & 7) << 4);
    const __half* gA = Ah + (size_t)(bm + r0) * K + c8 * 8;
    const __half* gB = Bh + (size_t)(bn + r0) * K + c8 * 8;

    // ldmatrix geometry
    const uint32_t axor = (uint32_t)(lane & 7) << 4;
    const uint32_t aRowBase = (uint32_t)(wm * 64 + (lane & 15)) * 128u;
    const uint32_t aK16 = ((lane >> 4) & 1) << 4;
    const uint32_t bRowBase = (uint32_t)(wn * 32 + (lane & 7) + (((lane >> 4) & 1) << 3)) * 128u;
    const uint32_t bK16 = ((lane >> 3) & 1) << 4;

    float acc[64];
    #pragma unroll
    for (int i = 0; i < 64; i++) acc[i] = 0.f;

    const int nst = K >> 6;      // chunks of 64

    #pragma unroll
    for (int st = 0; st < 3; st++) {
        if (st < nst) {
            const uint32_t sb = sbase + (uint32_t)(st & 3) * STAGE_BYTES;
            const size_t kk = (size_t)st * 64;
            #pragma unroll
            for (int c = 0; c < 4; c++) {
                uint32_t sr = (uint32_t)(r0 + c * 32) * 128u + so;
                const size_t go = kk + (size_t)c * 32 * K;
                cp16(sb + sr,         gA + go);
                cp16(sb + 16384 + sr, gB + go);
            }
        }
        asm volatile("cp.async.commit_group;" ::: "memory");
    }

    for (int it = 0; it < nst; it++) {
        const int st = it + 3;
        if (st < nst) {
            const uint32_t sb = sbase + (uint32_t)(st & 3) * STAGE_BYTES;
            const size_t kk = (size_t)st * 64;
            #pragma unroll
            for (int c = 0; c < 4; c++) {
                uint32_t sr = (uint32_t)(r0 + c * 32) * 128u + so;
                const size_t go = kk + (size_t)c * 32 * K;
                cp16(sb + sr,         gA + go);
                cp16(sb + 16384 + sr, gB + go);
            }
        }
        asm volatile("cp.async.commit_group;" ::: "memory");
        asm volatile("cp.async.wait_group 3;" ::: "memory");
        __syncthreads();

        const uint32_t stoff = (uint32_t)(it & 3) * STAGE_BYTES;
        const uint32_t aB = sbase + stoff + aRowBase;
        const uint32_t bB = sbase + stoff + 16384 + bRowBase;

        #pragma unroll
        for (int s = 0; s < 4; s++) {
            const uint32_t kc = (uint32_t)(s * 32);     // 16 halves = 32B per step
            uint32_t a[4][4], b[2][4];
            #pragma unroll
            for (int i = 0; i < 4; i++)
                ldsm4(a[i], aB + (uint32_t)(i * 2048) + ((kc + aK16) ^ axor));
            #pragma unroll
            for (int j = 0; j < 2; j++)
                ldsm4(b[j], bB + (uint32_t)(j * 2048) + ((kc + bK16) ^ axor));
            #pragma unroll
            for (int i = 0; i < 4; i++)
                #pragma unroll
                for (int j = 0; j < 4; j++)
                    mma16816(&acc[(i * 4 + j) * 4], a[i], &b[j >> 1][(j & 1) * 2]);
        }
        __syncthreads();
    }

    // ---- epilogue ------------------------------------------------------------
    const int r_base = bm + wm * 64 + (lane >> 2);
    const int c_base = bn + wn * 32 + (lane & 3) * 2;
    #pragma unroll
    for (int i = 0; i < 4; i++) {
        #pragma unroll
        for (int j = 0; j < 4; j++) {
            const float* d = &acc[(i * 4 + j) * 4];
            const int col = c_base + j * 8;
            #pragma unroll
            for (int hf = 0; hf < 2; hf++) {
                const int row = r_base + i * 16 + hf * 8;
                float v0 = d[hf * 2 + 0];
                float v1 = d[hf * 2 + 1];
                if (EPI == 0) {
                    *(float2*)(Cf + (size_t)row * N + col) = make_float2(v0, v1);
                } else if (EPI == 1) {
                    const size_t off = (size_t)row * N + col;
                    v0 += bias[col];
                    v1 += bias[col + 1];
                    v0 = v0 / (1.0f + expf(-v0));
                    v1 = v1 / (1.0f + expf(-v1));
                    *(__half2*)(Ch + off) = __floats2half2_rn(v0, v1);
                } else if (EPI == 2) {
                    const size_t off = (size_t)row * N + col;
                    v0 += bias[col]     + res[off];
                    v1 += bias[col + 1] + res[off + 1];
                    *(float2*)(Cf + off) = make_float2(v0, v1);
                } else {
                    if (blockIdx.x == 0) {
                        *(float2*)(Cf2 + (size_t)row * K2 + col) = make_float2(v0, v1);
                    } else {
                        const int gc = col - K2;
                        v0 = 1.0f / (1.0f + expf(-(v0 + bias[gc])));
                        v1 = 1.0f / (1.0f + expf(-(v1 + bias[gc + 1])));
                        *(__half2*)(Ch + (size_t)row * DDIM + gc) = __floats2half2_rn(v0, v1);
                    }
                }
            }
        }
    }
}

// ====== weight prep: W[K,N] fp32 -> W^T[N,K] fp16, tiled transpose ===========
__global__ void prep_w_t(const float* __restrict__ w, __half* __restrict__ hi,
                         int K, int N) {
    __shared__ float tile[32][33];
    const int k0 = blockIdx.x * 32;
    const int n0 = blockIdx.y * 32;
    const int tx = threadIdx.x, ty = threadIdx.y;
    #pragma unroll
    for (int i = ty; i < 32; i += 8)
        tile[i][tx] = w[(size_t)(k0 + i) * N + n0 + tx];
    __syncthreads();
    #pragma unroll
    for (int i = ty; i < 32; i += 8)
        hi[(size_t)(n0 + i) * K + k0 + tx] = __float2half_rn(tile[tx][i]);
}

// ================ LayerNorm -> fp16 ==========================================
__global__ void ln_kernel(const float* __restrict__ x, const float* __restrict__ g,
                          const float* __restrict__ b, __half* __restrict__ y) {
    int row = blockIdx.x;
    int tid = threadIdx.x;
    const float* xr = x + (size_t)row * DDIM;
    float v0 = xr[tid], v1 = xr[tid + 256];
    float s = v0 + v1, sq = v0 * v0 + v1 * v1;
    __shared__ float rs[8], rq[8];
    #pragma unroll
    for (int o = 16; o > 0; o >>= 1) {
        s  += __shfl_down_sync(0xffffffffu, s, o);
        sq += __shfl_down_sync(0xffffffffu, sq, o);
    }
    if ((tid & 31) == 0) { rs[tid >> 5] = s; rq[tid >> 5] = sq; }
    __syncthreads();
    __shared__ float mean_s, rstd_s;
    if (tid == 0) {
        float ts = 0.f, tq = 0.f;
        #pragma unroll
        for (int i = 0; i < 8; i++) { ts += rs[i]; tq += rq[i]; }
        float m = ts * (1.0f / DDIM);
        mean_s = m; rstd_s = rsqrtf(tq * (1.0f / DDIM) - m * m + 1e-5f);
    }
    __syncthreads();
    float m = mean_s, r = rstd_s;
    size_t base = (size_t)row * DDIM;
    y[base + tid]       = __float2half_rn((v0 - m) * r * g[tid]       + b[tid]);
    y[base + tid + 256] = __float2half_rn((v1 - m) * r * g[tid + 256] + b[tid + 256]);
}

// ====== fused: x1 = x + gate*h ; xn2 = LN(x1) -> fp16 ========================
__global__ void gate_ln_kernel(const float* __restrict__ x, const __half* __restrict__ gate,
                               const float* __restrict__ h,
                               const float* __restrict__ g2, const float* __restrict__ bn2,
                               float* __restrict__ x1, __half* __restrict__ y) {
    int row = blockIdx.x;
    int tid = threadIdx.x;
    size_t base = (size_t)row * DDIM;
    int c0 = tid, c1 = tid + 256;
    float v0 = x[base + c0] + __half2float(gate[base + c0]) * h[base + c0];
    float v1 = x[base + c1] + __half2float(gate[base + c1]) * h[base + c1];
    x1[base + c0] = v0;
    x1[base + c1] = v1;
    float s = v0 + v1, sq = v0 * v0 + v1 * v1;
    __shared__ float rs[8], rq[8];
    #pragma unroll
    for (int o = 16; o > 0; o >>= 1) {
        s  += __shfl_down_sync(0xffffffffu, s, o);
        sq += __shfl_down_sync(0xffffffffu, sq, o);
    }
    if ((tid & 31) == 0) { rs[tid >> 5] = s; rq[tid >> 5] = sq; }
    __syncthreads();
    __shared__ float mean_s, rstd_s;
    if (tid == 0) {
        float ts = 0.f, tq = 0.f;
        #pragma unroll
        for (int i = 0; i < 8; i++) { ts += rs[i]; tq += rq[i]; }
        float m = ts * (1.0f / DDIM);
        mean_s = m; rstd_s = rsqrtf(tq * (1.0f / DDIM) - m * m + 1e-5f);
    }
    __syncthreads();
    float m = mean_s, r = rstd_s;
    y[base + c0] = __float2half_rn((v0 - m) * r * g2[c0] + bn2[c0]);
    y[base + c1] = __float2half_rn((v1 - m) * r * g2[c1] + bn2[c1]);
}

// ------------- parallel complex linear recurrence (3-phase chunked scan) -----
__global__ void __launch_bounds__(1024, 1) scan_kernel(
    const float* __restrict__ beta, const float* __restrict__ log_decay,
    const float* __restrict__ freq, float* __restrict__ craw)
{
    __shared__ float carr_r[16 * 64], carr_i[16 * 64];
    __shared__ float pref_r[16 * 64], pref_i[16 * 64];
    const int b  = blockIdx.x;
    const int tid = threadIdx.x;
    const int ch = tid >> 6;
    const int k  = tid & 63;

    float mag = 1.0f / (1.0f + expf(-log_decay[k]));
    float sn, cs;
    sincosf(freq[k], &sn, &cs);
    const float lr = mag * cs, li = mag * sn;

    float pr = lr, pi = li;
    #pragma unroll
    for (int q = 0; q < 6; q++) {
        float nr = pr * pr - pi * pi;
        float ni = 2.f * pr * pi;
        pr = nr; pi = ni;
    }

    const size_t tok0 = (size_t)b * TDIM + ch * 64;
    float cr = 0.f, ci = 0.f;
    for (int i = 0; i < 64; i++) {
        const size_t o = (tok0 + i) * K2;
        float br = beta[o + k];
        float bi = beta[o + 64 + k];
        float nr = fmaf(lr, cr, fmaf(-li, ci, br));
        float ni = fmaf(lr, ci, fmaf(li, cr, bi));
        cr = nr; ci = ni;
        craw[o + k] = cr;
        craw[o + 64 + k] = ci;
    }
    carr_r[ch * 64 + k] = cr;
    carr_i[ch * 64 + k] = ci;
    __syncthreads();

    if (tid < 64) {
        float sr = 0.f, si = 0.f;
        #pragma unroll
        for (int j = 0; j < 16; j++) {
            pref_r[j * 64 + k] = sr;
            pref_i[j * 64 + k] = si;
            float nr = carr_r[j * 64 + k] + pr * sr - pi * si;
            float ni = carr_i[j * 64 + k] + pr * si + pi * sr;
            sr = nr; si = ni;
        }
    }
    __syncthreads();

    if (ch > 0) {
        float sr = pref_r[ch * 64 + k];
        float si = pref_i[ch * 64 + k];
        if (sr != 0.f || si != 0.f) {
            float fr = lr, fi = li;
            for (int i = 0; i < 64; i++) {
                const size_t o = (tok0 + i) * K2;
                float addr_ = fr * sr - fi * si;
                float addi_ = fr * si + fi * sr;
                craw[o + k]      += addr_;
                craw[o + 64 + k] += addi_;
                float nr = fr * lr - fi * li;
                float ni = fr * li + fi * lr;
                fr = nr; fi = ni;
            }
        }
    }
}

// -------- per-head coupling -> eig fp32 (output) + fp16 ---------------------
__global__ void coupling_kernel(const float* __restrict__ craw, const float* __restrict__ coup,
                                float* __restrict__ eig, __half* __restrict__ eh) {
    __shared__ float sc[HDIM * KPD * KPD];
    __shared__ float row[4 * K2];
    int tid = threadIdx.x;
    #pragma unroll
    for (int i = tid; i < HDIM * KPD * KPD; i += 256) sc[i] = coup[i];
    const float2* src = (const float2*)(craw + (size_t)blockIdx.x * 4 * K2);
    ((float2*)row)[tid] = src[tid];
    __syncthreads();
    int local = tid >> 6;
    int j = tid & 63;
    int h = j >> 4, jj = j & 15;
    const float* cp = &sc[h * 256 + jj * 16];
    const float* rr = &row[local * K2 + h * 16];
    float accr = 0.f, acci = 0.f;
    #pragma unroll
    for (int k = 0; k < 16; k++) {
        accr = fmaf(cp[k], rr[k], accr);
        acci = fmaf(cp[k], rr[k + 64], acci);
    }
    size_t token = (size_t)blockIdx.x * 4 + local;
    eig[token * K2 + j] = accr;
    eig[token * K2 + 64 + j] = acci;
    eh[token * K2 + j]      = __float2half_rn(accr);
    eh[token * K2 + 64 + j] = __float2half_rn(acci);
}

// =============================================================================
extern "C" void kernel_launch(void* const* d_in, const int* in_sizes, int n_in,
                              void* d_out, int out_size) {
    const float* x         = (const float*)d_in[0];
    const float* w_in      = (const float*)d_in[1];
    const float* log_decay = (const float*)d_in[2];
    const float* frequency = (const float*)d_in[3];
    const float* coupling  = (const float*)d_in[4];
    const float* w_out     = (const float*)d_in[5];
    const float* w_gate    = (const float*)d_in[6];
    const float* b_gate    = (const float*)d_in[7];
    const float* w1        = (const float*)d_in[8];
    const float* b1        = (const float*)d_in[9];
    const float* w2        = (const float*)d_in[10];
    const float* b2        = (const float*)d_in[11];
    const float* g1        = (const float*)d_in[12];
    const float* bn1       = (const float*)d_in[13];
    const float* g2        = (const float*)d_in[14];
    const float* bn2       = (const float*)d_in[15];

    float* out = (float*)d_out;
    float* eig = out + (size_t)BT * DDIM;

    float *beta, *craw, *hbuf, *x1;
    __half *gate, *xnh, *xn2h, *ehp, *t1h;
    __half *wch, *woh, *w1h, *w2h;
    cudaGetSymbolAddress((void**)&beta, g_beta);
    cudaGetSymbolAddress((void**)&craw, g_craw);
    cudaGetSymbolAddress((void**)&hbuf, g_h);
    cudaGetSymbolAddress((void**)&x1,   g_x1);
    cudaGetSymbolAddress((void**)&gate, g_gate);
    cudaGetSymbolAddress((void**)&xnh,  g_xn_h);
    cudaGetSymbolAddress((void**)&xn2h, g_xn2_h);
    cudaGetSymbolAddress((void**)&ehp,  g_eig_h);
    cudaGetSymbolAddress((void**)&t1h,  g_t1_h);
    cudaGetSymbolAddress((void**)&wch,  g_wc_h);
    cudaGetSymbolAddress((void**)&woh,  g_wo_h);
    cudaGetSymbolAddress((void**)&w1h,  g_w1_h);
    cudaGetSymbolAddress((void**)&w2h,  g_w2_h);

    const int SMEM = 4 * STAGE_BYTES;   // 128 KB
    cudaFuncSetAttribute(mma_gemm<0>, cudaFuncAttributeMaxDynamicSharedMemorySize, SMEM);
    cudaFuncSetAttribute(mma_gemm<1>, cudaFuncAttributeMaxDynamicSharedMemorySize, SMEM);
    cudaFuncSetAttribute(mma_gemm<2>, cudaFuncAttributeMaxDynamicSharedMemorySize, SMEM);
    cudaFuncSetAttribute(mma_gemm<3>, cudaFuncAttributeMaxDynamicSharedMemorySize, SMEM);

    // weight prep: tiled transpose + fp16
    dim3 tb(32, 8);
    prep_w_t<<<dim3(DDIM / 32, K2 / 32),   tb>>>(w_in,   wch,             DDIM, K2);
    prep_w_t<<<dim3(DDIM / 32, DDIM / 32), tb>>>(w_gate, wch + K2 * DDIM, DDIM, DDIM);
    prep_w_t<<<dim3(K2 / 32,   DDIM / 32), tb>>>(w_out,  woh,             K2,   DDIM);
    prep_w_t<<<dim3(DDIM / 32, MLPD / 32), tb>>>(w1,     w1h,             DDIM, MLPD);
    prep_w_t<<<dim3(MLPD / 32, DDIM / 32), tb>>>(w2,     w2h,             MLPD, DDIM);

    // 1. xn = LN(x) -> fp16
    ln_kernel<<<BT, 256>>>(x, g1, bn1, xnh);
    // 2+6 merged: [beta | gate] = xn @ [w_in | w_gate]; gate gets sigmoid+bias fused
    mma_gemm<3><<<dim3((K2 + DDIM) / 128, BT / 128), 256, SMEM>>>(
        xnh, wch, nullptr, gate, b_gate, nullptr, beta, BT, K2 + DDIM, DDIM);
    // 3. parallel chunked complex recurrence
    scan_kernel<<<BDIM, 1024>>>(beta, log_decay, frequency, craw);
    // 4. coupling -> eigenstates (output) + fp16
    coupling_kernel<<<BT / 4, 256>>>(craw, coupling, eig, ehp);
    // 5. h = eig @ w_out   [BT,128]x[128,512]
    mma_gemm<0><<<dim3(DDIM / 128, BT / 128), 256, SMEM>>>(
        ehp, woh, hbuf, nullptr, nullptr, nullptr, nullptr, BT, DDIM, K2);
    // 7. x1 = x + gate*h ; xn2 = LN(x1) -> fp16
    gate_ln_kernel<<<BT, 256>>>(x, gate, hbuf, g2, bn2, x1, xn2h);
    // 8. t1 = silu(xn2 @ w1 + b1) -> fp16   [BT,512]x[512,2048]
    mma_gemm<1><<<dim3(MLPD / 128, BT / 128), 256, SMEM>>>(
        xn2h, w1h, nullptr, t1h, b1, nullptr, nullptr, BT, MLPD, DDIM);
    // 9. out = x1 + t1 @ w2 + b2   [BT,2048]x[2048,512]
    mma_gemm<2><<<dim3(DDIM / 128, BT / 128), 256, SMEM>>>(
        t1h, w2h, out, nullptr, b2, x1, nullptr, BT, DDIM, MLPD);
}